// round 1
// baseline (speedup 1.0000x reference)
#include <cuda_runtime.h>

#define BB 2048
#define LL 8192
#define GG 256
#define BETA 0.01f

// Per-row partial sums (scratch; __device__ global, no allocation).
__device__ float g_block_sums[BB];

__global__ __launch_bounds__(256) void meta_row_kernel(
    const float* __restrict__ logits,
    const int*   __restrict__ true_y,
    const int*   __restrict__ group_ids)
{
    __shared__ float s_logp[GG];
    __shared__ int   s_any[GG];
    __shared__ float s_red[8];

    const int tid = threadIdx.x;
    const int row = blockIdx.x;

    s_logp[tid] = 0.0f;
    s_any[tid]  = 0;
    __syncthreads();

    const float4* lg4 = (const float4*)(logits + (size_t)row * LL);
    const int4*   ty4 = (const int4*)(true_y + (size_t)row * LL);
    const int4*   gi4 = (const int4*)group_ids;

    // 8192 elements / (256 threads * 4 per vec) = 8 iterations
    #pragma unroll
    for (int i = 0; i < 8; i++) {
        const int idx = tid + 256 * i;
        const float4 x = lg4[idx];
        const int4   y = ty4[idx];
        const int4   g = gi4[idx];

        // softplus(x) = max(x,0) + log(1 + exp(-|x|)); log_sigmoid(-x) = -softplus(x)
        const float sp0 = fmaxf(x.x, 0.0f) + __logf(1.0f + __expf(-fabsf(x.x)));
        const float sp1 = fmaxf(x.y, 0.0f) + __logf(1.0f + __expf(-fabsf(x.y)));
        const float sp2 = fmaxf(x.z, 0.0f) + __logf(1.0f + __expf(-fabsf(x.z)));
        const float sp3 = fmaxf(x.w, 0.0f) + __logf(1.0f + __expf(-fabsf(x.w)));

        atomicAdd(&s_logp[g.x], -sp0);
        atomicAdd(&s_logp[g.y], -sp1);
        atomicAdd(&s_logp[g.z], -sp2);
        atomicAdd(&s_logp[g.w], -sp3);

        // Benign race: everyone stores 1.
        if (y.x) s_any[g.x] = 1;
        if (y.y) s_any[g.y] = 1;
        if (y.z) s_any[g.z] = 1;
        if (y.w) s_any[g.w] = 1;
    }
    __syncthreads();

    // One thread per group computes its BCE term.
    const float gl = s_logp[tid];                   // grp_log[row, tid] (<= 0)
    float term;
    if (s_any[tid]) {
        term = fmaxf(gl, -100.0f);                  // meta_y = 1: log_p clamped
    } else {
        // log(1 - exp(gl)) computed accurately via expm1 (rare path)
        const float em = expm1f(gl);                // in (-1, 0]
        term = fmaxf(logf(fmaxf(-em, 1e-45f)), -100.0f);
    }

    // Block reduction of 256 terms.
    #pragma unroll
    for (int o = 16; o > 0; o >>= 1)
        term += __shfl_xor_sync(0xffffffffu, term, o);
    if ((tid & 31) == 0) s_red[tid >> 5] = term;
    __syncthreads();
    if (tid < 8) {
        float v = s_red[tid];
        #pragma unroll
        for (int o = 4; o > 0; o >>= 1)
            v += __shfl_xor_sync(0x000000ffu, v, o);
        if (tid == 0) g_block_sums[row] = v;
    }
}

__global__ __launch_bounds__(256) void meta_final_kernel(float* __restrict__ out)
{
    __shared__ float s_red[8];
    const int tid = threadIdx.x;
    float v = 0.0f;
    #pragma unroll
    for (int i = tid; i < BB; i += 256)
        v += g_block_sums[i];
    #pragma unroll
    for (int o = 16; o > 0; o >>= 1)
        v += __shfl_xor_sync(0xffffffffu, v, o);
    if ((tid & 31) == 0) s_red[tid >> 5] = v;
    __syncthreads();
    if (tid == 0) {
        float s = 0.0f;
        #pragma unroll
        for (int i = 0; i < 8; i++) s += s_red[i];
        out[0] = -s / (float)(BB * GG) * BETA;
    }
}

extern "C" void kernel_launch(void* const* d_in, const int* in_sizes, int n_in,
                              void* d_out, int out_size)
{
    const float* logits    = (const float*)d_in[0];
    const int*   true_y    = (const int*)d_in[1];
    const int*   group_ids = (const int*)d_in[2];
    float* out = (float*)d_out;

    meta_row_kernel<<<BB, 256>>>(logits, true_y, group_ids);
    meta_final_kernel<<<1, 256>>>(out);
}

// round 3
// speedup vs baseline: 1.3033x; 1.3033x over previous
#include <cuda_runtime.h>

#define BB 2048
#define LL 8192
#define GG 256
#define BETA 0.01f

// Precomputed label layout (recomputed every launch; __device__ globals = legal scratch).
__device__ int g_start[GG + 1];   // group segment offsets (exclusive prefix), g_start[GG] = LL
__device__ int g_dest[LL];        // packed: slot | (group << 16)

// XOR swizzle on word index: makes stride-~32 segment reads conflict-free,
// random scatter stores stay random. Bijective on [0, LL).
__device__ __forceinline__ int SW(int w) { return w ^ ((w >> 5) & 31); }

__global__ __launch_bounds__(256) void setup_kernel(const int* __restrict__ gid)
{
    __shared__ int cnt[GG];
    __shared__ int cnt2[GG];
    __shared__ int start_s[GG];
    __shared__ int wsum[8];

    const int t = threadIdx.x;
    cnt[t] = 0;
    cnt2[t] = 0;
    __syncthreads();

    #pragma unroll
    for (int i = t; i < LL; i += 256)
        atomicAdd(&cnt[gid[i]], 1);
    __syncthreads();

    // Exclusive prefix sum over 256 counts.
    const int lane = t & 31, wid = t >> 5;
    const int v = cnt[t];
    int s = v;
    #pragma unroll
    for (int o = 1; o < 32; o <<= 1) {
        int u = __shfl_up_sync(0xffffffffu, s, o);
        if (lane >= o) s += u;
    }
    if (lane == 31) wsum[wid] = s;
    __syncthreads();
    int off = 0;
    #pragma unroll
    for (int w = 0; w < 8; w++)
        if (w < wid) off += wsum[w];
    const int excl = off + s - v;
    start_s[t] = excl;
    g_start[t] = excl;
    if (t == 255) g_start[GG] = LL;
    __syncthreads();

    #pragma unroll
    for (int i = t; i < LL; i += 256) {
        const int g = gid[i];
        const int r = atomicAdd(&cnt2[g], 1);
        g_dest[i] = (start_s[g] + r) | (g << 16);
    }
}

__global__ __launch_bounds__(256) void meta_row_kernel(
    const float* __restrict__ logits,
    const int*   __restrict__ true_y,
    float*       __restrict__ out)
{
    __shared__ float         s_vals[LL];   // 32 KB, grouped-by-segment (swizzled)
    __shared__ unsigned char s_any[GG];
    __shared__ float         s_red[8];

    const int tid = threadIdx.x;
    const int row = blockIdx.x;

    s_any[tid] = 0;
    __syncthreads();

    const float4* lg4 = (const float4*)(logits + (size_t)row * LL);
    const int4*   ty4 = (const int4*)(true_y + (size_t)row * LL);
    const int4*   dd4 = (const int4*)g_dest;

    #pragma unroll
    for (int i = 0; i < 8; i++) {
        const int idx = tid + 256 * i;
        const float4 x = lg4[idx];
        const int4   y = ty4[idx];
        const int4   d = dd4[idx];

        // log_sigmoid(-x) = -softplus(x) = -(max(x,0) + log(1 + exp(-|x|)))
        const float v0 = -(fmaxf(x.x, 0.0f) + __logf(1.0f + __expf(-fabsf(x.x))));
        const float v1 = -(fmaxf(x.y, 0.0f) + __logf(1.0f + __expf(-fabsf(x.y))));
        const float v2 = -(fmaxf(x.z, 0.0f) + __logf(1.0f + __expf(-fabsf(x.z))));
        const float v3 = -(fmaxf(x.w, 0.0f) + __logf(1.0f + __expf(-fabsf(x.w))));

        s_vals[SW(d.x & 0xFFFF)] = v0;
        s_vals[SW(d.y & 0xFFFF)] = v1;
        s_vals[SW(d.z & 0xFFFF)] = v2;
        s_vals[SW(d.w & 0xFFFF)] = v3;

        // Benign race: all writers store 1.
        if (y.x) s_any[d.x >> 16] = 1;
        if (y.y) s_any[d.y >> 16] = 1;
        if (y.z) s_any[d.z >> 16] = 1;
        if (y.w) s_any[d.w >> 16] = 1;
    }
    __syncthreads();

    // Phase 2: thread g reduces its group's contiguous segment.
    const int st = g_start[tid];
    const int en = g_start[tid + 1];
    float gl = 0.0f;
    for (int i = st; i < en; i++)
        gl += s_vals[SW(i)];

    float term;
    if (s_any[tid]) {
        term = fmaxf(gl, -100.0f);                    // meta_y = 1
    } else {
        const float em = expm1f(gl);                  // accurate log(1 - exp(gl))
        term = fmaxf(logf(fmaxf(-em, 1e-45f)), -100.0f);
    }

    // Block reduction, then one atomic per row into the scalar output.
    #pragma unroll
    for (int o = 16; o > 0; o >>= 1)
        term += __shfl_xor_sync(0xffffffffu, term, o);
    if ((tid & 31) == 0) s_red[tid >> 5] = term;
    __syncthreads();
    if (tid < 8) {
        float v = s_red[tid];
        #pragma unroll
        for (int o = 4; o > 0; o >>= 1)
            v += __shfl_xor_sync(0x000000ffu, v, o);
        if (tid == 0)
            atomicAdd(out, v * (-BETA / (float)(BB * GG)));
    }
}

extern "C" void kernel_launch(void* const* d_in, const int* in_sizes, int n_in,
                              void* d_out, int out_size)
{
    const float* logits    = (const float*)d_in[0];
    const int*   true_y    = (const int*)d_in[1];
    const int*   group_ids = (const int*)d_in[2];
    float* out = (float*)d_out;

    cudaMemsetAsync(d_out, 0, sizeof(float));
    setup_kernel<<<1, 256>>>(group_ids);
    meta_row_kernel<<<BB, 256>>>(logits, true_y, out);
}